// round 2
// baseline (speedup 1.0000x reference)
#include <cuda_runtime.h>
#include <cuda_bf16.h>
#include <math.h>

// Problem constants
#define BATCH 4
#define SEQ   2048
#define EMB   1024
#define HEADS 16
#define HD    64
#define MROWS (BATCH * SEQ)   // 8192

// Scratch: Q,K,V in [b,h,s,d], attn-out in [b,s,h,d] (== [M, E] row-major)
__device__ float g_q[MROWS * EMB];
__device__ float g_k[MROWS * EMB];
__device__ float g_v[MROWS * EMB];
__device__ float g_a[MROWS * EMB];

// ---------------------------------------------------------------------------
// Fused QKV GEMM: for z = blockIdx.z in {0,1,2}, C_z[m,n] = sum_k A[m,k]*W_z[n,k]
// scattering into [b,h,s,d] layout. Tiles: 128x128x8, 256 threads, 8x8 microtile.
// ---------------------------------------------------------------------------
__global__ __launch_bounds__(256, 2)
void gemm_qkv(const float* __restrict__ A,
              const float* __restrict__ Wq, const float* __restrict__ Wk,
              const float* __restrict__ Wv,
              float* __restrict__ Cq, float* __restrict__ Ck,
              float* __restrict__ Cv)
{
    __shared__ float As[8][128];
    __shared__ float Bs[8][128];

    const float* W = (blockIdx.z == 0) ? Wq : (blockIdx.z == 1) ? Wk : Wv;
    float*       C = (blockIdx.z == 0) ? Cq : (blockIdx.z == 1) ? Ck : Cv;

    const int K = EMB;
    int tid = threadIdx.x;
    int tx = tid & 15, ty = tid >> 4;
    int bm = blockIdx.x * 128;
    int bn = blockIdx.y * 128;

    float acc[8][8];
#pragma unroll
    for (int i = 0; i < 8; i++)
#pragma unroll
        for (int j = 0; j < 8; j++) acc[i][j] = 0.0f;

    int lrow = tid >> 1;          // 0..127
    int lk   = (tid & 1) * 4;     // 0 or 4
    const float* Aptr = A + (size_t)(bm + lrow) * K + lk;
    const float* Wptr = W + (size_t)(bn + lrow) * K + lk;

    for (int k0 = 0; k0 < K; k0 += 8) {
        float4 av = *(const float4*)(Aptr + k0);
        float4 bv = *(const float4*)(Wptr + k0);
        __syncthreads();
        As[lk + 0][lrow] = av.x; As[lk + 1][lrow] = av.y;
        As[lk + 2][lrow] = av.z; As[lk + 3][lrow] = av.w;
        Bs[lk + 0][lrow] = bv.x; Bs[lk + 1][lrow] = bv.y;
        Bs[lk + 2][lrow] = bv.z; Bs[lk + 3][lrow] = bv.w;
        __syncthreads();

#pragma unroll
        for (int kk = 0; kk < 8; kk++) {
            float a[8], b[8];
            float4 t;
            t = *(const float4*)&As[kk][ty * 8];     a[0]=t.x; a[1]=t.y; a[2]=t.z; a[3]=t.w;
            t = *(const float4*)&As[kk][ty * 8 + 4]; a[4]=t.x; a[5]=t.y; a[6]=t.z; a[7]=t.w;
            t = *(const float4*)&Bs[kk][tx * 8];     b[0]=t.x; b[1]=t.y; b[2]=t.z; b[3]=t.w;
            t = *(const float4*)&Bs[kk][tx * 8 + 4]; b[4]=t.x; b[5]=t.y; b[6]=t.z; b[7]=t.w;
#pragma unroll
            for (int i = 0; i < 8; i++)
#pragma unroll
                for (int j = 0; j < 8; j++)
                    acc[i][j] += a[i] * b[j];
        }
    }

    int c0 = bn + tx * 8;
    int h  = c0 >> 6;
    int d0 = c0 & 63;
#pragma unroll
    for (int i = 0; i < 8; i++) {
        int r = bm + ty * 8 + i;
        int bb_ = r >> 11;       // r / SEQ
        int s   = r & 2047;      // r % SEQ
        float* dst = C + ((((size_t)bb_ * HEADS + h) * SEQ + s) * HD + d0);
        float4 o0 = make_float4(acc[i][0], acc[i][1], acc[i][2], acc[i][3]);
        float4 o1 = make_float4(acc[i][4], acc[i][5], acc[i][6], acc[i][7]);
        *(float4*)dst = o0;
        *(float4*)(dst + 4) = o1;
    }
}

// ---------------------------------------------------------------------------
// Output GEMM: C[m,n] = sum_k A[m,k] * W[n,k] + bias[n]
// ---------------------------------------------------------------------------
__global__ __launch_bounds__(256, 2)
void gemm_out(const float* __restrict__ A, const float* __restrict__ W,
              float* __restrict__ C, const float* __restrict__ bias)
{
    __shared__ float As[8][128];
    __shared__ float Bs[8][128];

    const int K = EMB;
    int tid = threadIdx.x;
    int tx = tid & 15, ty = tid >> 4;
    int bm = blockIdx.x * 128;
    int bn = blockIdx.y * 128;

    float acc[8][8];
#pragma unroll
    for (int i = 0; i < 8; i++)
#pragma unroll
        for (int j = 0; j < 8; j++) acc[i][j] = 0.0f;

    int lrow = tid >> 1;
    int lk   = (tid & 1) * 4;
    const float* Aptr = A + (size_t)(bm + lrow) * K + lk;
    const float* Wptr = W + (size_t)(bn + lrow) * K + lk;

    for (int k0 = 0; k0 < K; k0 += 8) {
        float4 av = *(const float4*)(Aptr + k0);
        float4 bv = *(const float4*)(Wptr + k0);
        __syncthreads();
        As[lk + 0][lrow] = av.x; As[lk + 1][lrow] = av.y;
        As[lk + 2][lrow] = av.z; As[lk + 3][lrow] = av.w;
        Bs[lk + 0][lrow] = bv.x; Bs[lk + 1][lrow] = bv.y;
        Bs[lk + 2][lrow] = bv.z; Bs[lk + 3][lrow] = bv.w;
        __syncthreads();

#pragma unroll
        for (int kk = 0; kk < 8; kk++) {
            float a[8], b[8];
            float4 t;
            t = *(const float4*)&As[kk][ty * 8];     a[0]=t.x; a[1]=t.y; a[2]=t.z; a[3]=t.w;
            t = *(const float4*)&As[kk][ty * 8 + 4]; a[4]=t.x; a[5]=t.y; a[6]=t.z; a[7]=t.w;
            t = *(const float4*)&Bs[kk][tx * 8];     b[0]=t.x; b[1]=t.y; b[2]=t.z; b[3]=t.w;
            t = *(const float4*)&Bs[kk][tx * 8 + 4]; b[4]=t.x; b[5]=t.y; b[6]=t.z; b[7]=t.w;
#pragma unroll
            for (int i = 0; i < 8; i++)
#pragma unroll
                for (int j = 0; j < 8; j++)
                    acc[i][j] += a[i] * b[j];
        }
    }

    int c0 = bn + tx * 8;
    float bb[8];
#pragma unroll
    for (int j = 0; j < 8; j++) bb[j] = bias[c0 + j];
#pragma unroll
    for (int i = 0; i < 8; i++) {
        int r = bm + ty * 8 + i;
        float4 o0 = make_float4(acc[i][0] + bb[0], acc[i][1] + bb[1],
                                acc[i][2] + bb[2], acc[i][3] + bb[3]);
        float4 o1 = make_float4(acc[i][4] + bb[4], acc[i][5] + bb[5],
                                acc[i][6] + bb[6], acc[i][7] + bb[7]);
        float* dst = C + (size_t)r * EMB + c0;
        *(float4*)dst = o0;
        *(float4*)(dst + 4) = o1;
    }
}

// ---------------------------------------------------------------------------
// Causal flash attention (fp32). Q,K,V in [b,h,s,d]; O in [b,s,h,d].
// Block: 256 threads, BQ=64 queries, BK=32 keys per step.
// ---------------------------------------------------------------------------
#define BQ 64
#define BK 32

__global__ __launch_bounds__(256)
void attn_kernel(const float* __restrict__ Q, const float* __restrict__ K,
                 const float* __restrict__ V, float* __restrict__ O)
{
    __shared__ float Qs[64][64];   // [d][q]
    __shared__ float Ks[64][34];   // [d][k], padded
    __shared__ float Vs[32][64];   // [j][d]
    __shared__ float Ps[32][64];   // [j][q]

    int tid = threadIdx.x;
    int tx = tid & 15, ty = tid >> 4;
    int bh = blockIdx.y;                 // b*H + h
    int q0 = blockIdx.x * BQ;

    const float* Qb = Q + (size_t)bh * SEQ * HD;
    const float* Kb = K + (size_t)bh * SEQ * HD;
    const float* Vb = V + (size_t)bh * SEQ * HD;

    // Load Q tile transposed: Qs[d][q]
    {
        int q = tid >> 2;            // 0..63
        int dbase = (tid & 3) * 16;  // 0,16,32,48
#pragma unroll
        for (int i = 0; i < 4; i++) {
            float4 v4 = *(const float4*)&Qb[(size_t)(q0 + q) * HD + dbase + i * 4];
            Qs[dbase + i * 4 + 0][q] = v4.x;
            Qs[dbase + i * 4 + 1][q] = v4.y;
            Qs[dbase + i * 4 + 2][q] = v4.z;
            Qs[dbase + i * 4 + 3][q] = v4.w;
        }
    }

    float m_row[4], l_row[4], acc[4][4];
#pragma unroll
    for (int i = 0; i < 4; i++) {
        m_row[i] = -INFINITY; l_row[i] = 0.0f;
#pragma unroll
        for (int j = 0; j < 4; j++) acc[i][j] = 0.0f;
    }

    const float scale = 0.125f;  // 1/sqrt(64)
    int nkb = (q0 + BQ) / BK;

    int kr = tid >> 3;            // 0..31
    int dbase = (tid & 7) * 8;    // 0..56

    for (int kb = 0; kb < nkb; kb++) {
        int k0 = kb * BK;

        float4 kv0 = *(const float4*)&Kb[(size_t)(k0 + kr) * HD + dbase];
        float4 kv1 = *(const float4*)&Kb[(size_t)(k0 + kr) * HD + dbase + 4];
        float4 vv0 = *(const float4*)&Vb[(size_t)(k0 + kr) * HD + dbase];
        float4 vv1 = *(const float4*)&Vb[(size_t)(k0 + kr) * HD + dbase + 4];

        __syncthreads();   // previous iteration fully consumed Ks/Vs/Ps
        Ks[dbase + 0][kr] = kv0.x; Ks[dbase + 1][kr] = kv0.y;
        Ks[dbase + 2][kr] = kv0.z; Ks[dbase + 3][kr] = kv0.w;
        Ks[dbase + 4][kr] = kv1.x; Ks[dbase + 5][kr] = kv1.y;
        Ks[dbase + 6][kr] = kv1.z; Ks[dbase + 7][kr] = kv1.w;
        *(float4*)&Vs[kr][dbase]     = vv0;
        *(float4*)&Vs[kr][dbase + 4] = vv1;
        __syncthreads();

        // Scores: s[4 rows][2 keys]
        float s[4][2];
#pragma unroll
        for (int i = 0; i < 4; i++) { s[i][0] = 0.0f; s[i][1] = 0.0f; }
#pragma unroll
        for (int d = 0; d < 64; d++) {
            float4 a = *(const float4*)&Qs[d][ty * 4];
            float2 b = *(const float2*)&Ks[d][tx * 2];
            s[0][0] += a.x * b.x; s[0][1] += a.x * b.y;
            s[1][0] += a.y * b.x; s[1][1] += a.y * b.y;
            s[2][0] += a.z * b.x; s[2][1] += a.z * b.y;
            s[3][0] += a.w * b.x; s[3][1] += a.w * b.y;
        }

        bool need_mask = (k0 + BK - 1) > q0;
#pragma unroll
        for (int i = 0; i < 4; i++) {
            int qi = q0 + ty * 4 + i;
#pragma unroll
            for (int j = 0; j < 2; j++) {
                s[i][j] *= scale;
                if (need_mask && (k0 + tx * 2 + j) > qi) s[i][j] = -INFINITY;
            }
        }

        // Row max over block (16 lanes share a row group)
        float mb[4];
#pragma unroll
        for (int i = 0; i < 4; i++) {
            mb[i] = fmaxf(s[i][0], s[i][1]);
            mb[i] = fmaxf(mb[i], __shfl_xor_sync(0xffffffffu, mb[i], 1));
            mb[i] = fmaxf(mb[i], __shfl_xor_sync(0xffffffffu, mb[i], 2));
            mb[i] = fmaxf(mb[i], __shfl_xor_sync(0xffffffffu, mb[i], 4));
            mb[i] = fmaxf(mb[i], __shfl_xor_sync(0xffffffffu, mb[i], 8));
        }

        float p[4][2];
#pragma unroll
        for (int i = 0; i < 4; i++) {
            float m_new = fmaxf(m_row[i], mb[i]);
            float fac = __expf(m_row[i] - m_new);   // exp(-inf)=0 first time
            p[i][0] = __expf(s[i][0] - m_new);
            p[i][1] = __expf(s[i][1] - m_new);
            float rs = p[i][0] + p[i][1];
            rs += __shfl_xor_sync(0xffffffffu, rs, 1);
            rs += __shfl_xor_sync(0xffffffffu, rs, 2);
            rs += __shfl_xor_sync(0xffffffffu, rs, 4);
            rs += __shfl_xor_sync(0xffffffffu, rs, 8);
            l_row[i] = l_row[i] * fac + rs;
            m_row[i] = m_new;
            acc[i][0] *= fac; acc[i][1] *= fac; acc[i][2] *= fac; acc[i][3] *= fac;
        }

        // Ps[j][q]
#pragma unroll
        for (int i = 0; i < 4; i++) {
            Ps[tx * 2 + 0][ty * 4 + i] = p[i][0];
            Ps[tx * 2 + 1][ty * 4 + i] = p[i][1];
        }
        __syncthreads();

        // O += P @ V
#pragma unroll
        for (int j = 0; j < 32; j++) {
            float4 a = *(const float4*)&Ps[j][ty * 4];
            float4 b = *(const float4*)&Vs[j][tx * 4];
            acc[0][0] += a.x * b.x; acc[0][1] += a.x * b.y; acc[0][2] += a.x * b.z; acc[0][3] += a.x * b.w;
            acc[1][0] += a.y * b.x; acc[1][1] += a.y * b.y; acc[1][2] += a.y * b.z; acc[1][3] += a.y * b.w;
            acc[2][0] += a.z * b.x; acc[2][1] += a.z * b.y; acc[2][2] += a.z * b.z; acc[2][3] += a.z * b.w;
            acc[3][0] += a.w * b.x; acc[3][1] += a.w * b.y; acc[3][2] += a.w * b.z; acc[3][3] += a.w * b.w;
        }
    }

    // Epilogue: normalize, write O in [b,s,h,d]
    int b = bh >> 4, h = bh & 15;
#pragma unroll
    for (int i = 0; i < 4; i++) {
        float inv = 1.0f / l_row[i];
        int sidx = q0 + ty * 4 + i;
        float4 o = make_float4(acc[i][0] * inv, acc[i][1] * inv,
                               acc[i][2] * inv, acc[i][3] * inv);
        float* dst = O + (((size_t)b * SEQ + sidx) * HEADS + h) * HD + tx * 4;
        *(float4*)dst = o;
    }
}

// ---------------------------------------------------------------------------
extern "C" void kernel_launch(void* const* d_in, const int* in_sizes, int n_in,
                              void* d_out, int out_size)
{
    const float* x  = (const float*)d_in[0];
    const float* Wq = (const float*)d_in[1];
    const float* Wk = (const float*)d_in[2];
    const float* Wv = (const float*)d_in[3];
    const float* Wo = (const float*)d_in[4];
    const float* bo = (const float*)d_in[5];
    float* out = (float*)d_out;

    float *q, *k, *v, *a;
    cudaGetSymbolAddress((void**)&q, g_q);
    cudaGetSymbolAddress((void**)&k, g_k);
    cudaGetSymbolAddress((void**)&v, g_v);
    cudaGetSymbolAddress((void**)&a, g_a);

    dim3 qkv_grid(MROWS / 128, EMB / 128, 3);   // 64 x 8 x 3
    gemm_qkv<<<qkv_grid, 256>>>(x, Wq, Wk, Wv, q, k, v);

    dim3 attn_grid(SEQ / BQ, BATCH * HEADS);    // 32 x 64
    attn_kernel<<<attn_grid, 256>>>(q, k, v, a);

    dim3 out_grid(MROWS / 128, EMB / 128);      // 64 x 8
    gemm_out<<<out_grid, 256>>>(a, Wo, out, bo);
}

// round 4
// speedup vs baseline: 1.5456x; 1.5456x over previous
#include <cuda_runtime.h>
#include <cuda_bf16.h>
#include <math.h>
#include <stdint.h>

// Problem constants
#define BATCH 4
#define SEQ   2048
#define EMB   1024
#define HEADS 16
#define HD    64
#define MROWS (BATCH * SEQ)   // 8192

// fp32 scratch
__device__ float g_q[MROWS * EMB];
__device__ float g_k[MROWS * EMB];
__device__ float g_v[MROWS * EMB];
__device__ float g_a[MROWS * EMB];
// bf16 split scratch
__device__ __nv_bfloat16 g_xhi[MROWS * EMB];
__device__ __nv_bfloat16 g_xlo[MROWS * EMB];
__device__ __nv_bfloat16 g_whi[4 * EMB * EMB];
__device__ __nv_bfloat16 g_wlo[4 * EMB * EMB];
__device__ __nv_bfloat16 g_ahi[MROWS * EMB];
__device__ __nv_bfloat16 g_alo[MROWS * EMB];

// ---------------------------------------------------------------------------
// warp-mma helpers (generic PTX: ldmatrix sm_75+, mma bf16 sm_80+)
// ---------------------------------------------------------------------------
__device__ __forceinline__ uint32_t smem_u32(const void* p) {
    uint32_t a;
    asm("{ .reg .u64 t; cvta.to.shared.u64 t, %1; cvt.u32.u64 %0, t; }" : "=r"(a) : "l"(p));
    return a;
}
__device__ __forceinline__ void ldm_x4(uint32_t* r, uint32_t addr) {
    asm volatile("ldmatrix.sync.aligned.m8n8.x4.shared.b16 {%0,%1,%2,%3}, [%4];"
                 : "=r"(r[0]), "=r"(r[1]), "=r"(r[2]), "=r"(r[3]) : "r"(addr));
}
__device__ __forceinline__ void mma16816(float* c, const uint32_t* a, uint32_t b0, uint32_t b1) {
    asm volatile(
        "mma.sync.aligned.m16n8k16.row.col.f32.bf16.bf16.f32 "
        "{%0,%1,%2,%3}, {%4,%5,%6,%7}, {%8,%9}, {%0,%1,%2,%3};"
        : "+f"(c[0]), "+f"(c[1]), "+f"(c[2]), "+f"(c[3])
        : "r"(a[0]), "r"(a[1]), "r"(a[2]), "r"(a[3]), "r"(b0), "r"(b1));
}

// ---------------------------------------------------------------------------
// fp32 -> (bf16 hi, bf16 lo) split conversion
// ---------------------------------------------------------------------------
__device__ __forceinline__ void split2(float a, float b, uint32_t& hi, uint32_t& lo) {
    __nv_bfloat16 ha = __float2bfloat16(a);
    __nv_bfloat16 hb = __float2bfloat16(b);
    __nv_bfloat16 la = __float2bfloat16(a - __bfloat162float(ha));
    __nv_bfloat16 lb = __float2bfloat16(b - __bfloat162float(hb));
    __nv_bfloat162 h2 = __nv_bfloat162(ha, hb);
    __nv_bfloat162 l2 = __nv_bfloat162(la, lb);
    hi = *(uint32_t*)&h2;
    lo = *(uint32_t*)&l2;
}

__global__ void conv_split(const float* __restrict__ in,
                           __nv_bfloat16* __restrict__ hi, __nv_bfloat16* __restrict__ lo) {
    int i = (blockIdx.x * blockDim.x + threadIdx.x) * 4;
    float4 v = *(const float4*)(in + i);
    uint32_t h0, l0, h1, l1;
    split2(v.x, v.y, h0, l0);
    split2(v.z, v.w, h1, l1);
    *(uint2*)((char*)hi + (size_t)i * 2) = make_uint2(h0, h1);
    *(uint2*)((char*)lo + (size_t)i * 2) = make_uint2(l0, l1);
}

__global__ void conv_w4(const float* __restrict__ Wq, const float* __restrict__ Wk,
                        const float* __restrict__ Wv, const float* __restrict__ Wo,
                        __nv_bfloat16* __restrict__ hi, __nv_bfloat16* __restrict__ lo) {
    int z = blockIdx.y;
    const float* W = (z == 0) ? Wq : (z == 1) ? Wk : (z == 2) ? Wv : Wo;
    size_t off = (size_t)z * EMB * EMB;
    int i = (blockIdx.x * blockDim.x + threadIdx.x) * 4;
    float4 v = *(const float4*)(W + i);
    uint32_t h0, l0, h1, l1;
    split2(v.x, v.y, h0, l0);
    split2(v.z, v.w, h1, l1);
    *(uint2*)((char*)(hi + off) + (size_t)i * 2) = make_uint2(h0, h1);
    *(uint2*)((char*)(lo + off) + (size_t)i * 2) = make_uint2(l0, l1);
}

// ---------------------------------------------------------------------------
// Tensor-core GEMM via mma.sync: C[m,n] = sum_k A[m,k]*W[n,k], 3x bf16 split.
// CTA 128x128, 8 warps (2x4), warp tile 64x32, K chunk 64, SMEM pad-72.
// mode 0: z selects weight; scatter to [b,h,s,d].  mode 1: row-major + bias.
// ---------------------------------------------------------------------------
#define SA 72                                // bf16 elems per SMEM row (144 B)
#define GEMM_SMEM (4 * 128 * SA * 2)         // Ahi, Alo, Bhi, Blo = 73728 B

__global__ __launch_bounds__(256, 1)
void wm_gemm(const __nv_bfloat16* __restrict__ Ahi, const __nv_bfloat16* __restrict__ Alo,
             const __nv_bfloat16* __restrict__ Whi, const __nv_bfloat16* __restrict__ Wlo,
             float* __restrict__ Cq, float* __restrict__ Ck, float* __restrict__ Cv,
             const float* __restrict__ bias, int mode)
{
    extern __shared__ char smem[];
    char* sAh = smem;
    char* sAl = smem + 128 * SA * 2;
    char* sBh = smem + 2 * 128 * SA * 2;
    char* sBl = smem + 3 * 128 * SA * 2;

    int tid = threadIdx.x, lane = tid & 31, wid = tid >> 5;
    int wm = (wid >> 2) * 64;        // 0 or 64
    int wn = (wid & 3) * 32;         // 0,32,64,96
    int bm = blockIdx.x * 128, bn = blockIdx.y * 128;
    int z = blockIdx.z;
    const char* gAh = (const char*)(Ahi + (size_t)bm * EMB);
    const char* gAl = (const char*)(Alo + (size_t)bm * EMB);
    const char* gBh = (const char*)(Whi + (size_t)z * EMB * EMB + (size_t)bn * EMB);
    const char* gBl = (const char*)(Wlo + (size_t)z * EMB * EMB + (size_t)bn * EMB);
    float* C = (mode == 1) ? Cq : ((z == 0) ? Cq : (z == 1) ? Ck : Cv);

    float acc[4][4][4];
#pragma unroll
    for (int mt = 0; mt < 4; mt++)
#pragma unroll
        for (int nt = 0; nt < 4; nt++)
#pragma unroll
            for (int e = 0; e < 4; e++) acc[mt][nt][e] = 0.0f;

    uint32_t uAh = smem_u32(sAh), uAl = smem_u32(sAl);
    uint32_t uBh = smem_u32(sBh), uBl = smem_u32(sBl);

    // ldmatrix base addresses for this lane
    // A x4: row = lane&15, k-offset = (lane>>4)*8  (elems)
    uint32_t aoff = (uint32_t)((lane & 15) * SA + (lane >> 4) * 8) * 2;
    // B x4: n-row = (lane>>4)*8 + (lane&7), k-offset = ((lane>>3)&1)*8
    uint32_t boff = (uint32_t)(((lane >> 4) * 8 + (lane & 7)) * SA + ((lane >> 3) & 1) * 8) * 2;

    int crow = tid >> 3, cseg = tid & 7;      // copy: 32 rows/iter, 8 x 16B segs/row

    for (int c = 0; c < 16; c++) {
        size_t goff = (size_t)c * 128;        // 64 bf16 = 128 B per chunk
        // load gmem -> regs
        uint4 va[4], vb[4], vc[4], vd[4];
#pragma unroll
        for (int i = 0; i < 4; i++) {
            size_t so = (size_t)(crow + i * 32) * 2048 + goff + cseg * 16;
            va[i] = *(const uint4*)(gAh + so);
            vb[i] = *(const uint4*)(gAl + so);
            vc[i] = *(const uint4*)(gBh + so);
            vd[i] = *(const uint4*)(gBl + so);
        }
        __syncthreads();
#pragma unroll
        for (int i = 0; i < 4; i++) {
            uint32_t doff = (uint32_t)(crow + i * 32) * (SA * 2) + cseg * 16;
            *(uint4*)(sAh + doff) = va[i];
            *(uint4*)(sAl + doff) = vb[i];
            *(uint4*)(sBh + doff) = vc[i];
            *(uint4*)(sBl + doff) = vd[i];
        }
        __syncthreads();

#pragma unroll
        for (int kk = 0; kk < 4; kk++) {
            uint32_t kb = (uint32_t)(kk * 16) * 2;
            uint32_t bh[8], bl[8];
            ldm_x4(bh + 0, uBh + boff + (uint32_t)(wn)      * (SA * 2) + kb);
            ldm_x4(bh + 4, uBh + boff + (uint32_t)(wn + 16) * (SA * 2) + kb);
            ldm_x4(bl + 0, uBl + boff + (uint32_t)(wn)      * (SA * 2) + kb);
            ldm_x4(bl + 4, uBl + boff + (uint32_t)(wn + 16) * (SA * 2) + kb);
#pragma unroll
            for (int mt = 0; mt < 4; mt++) {
                uint32_t ah[4], al[4];
                uint32_t arow = aoff + (uint32_t)(wm + mt * 16) * (SA * 2) + kb;
                ldm_x4(ah, uAh + arow);
                ldm_x4(al, uAl + arow);
#pragma unroll
                for (int nt = 0; nt < 4; nt++) {
                    mma16816(acc[mt][nt], ah, bh[nt * 2], bh[nt * 2 + 1]);
                    mma16816(acc[mt][nt], ah, bl[nt * 2], bl[nt * 2 + 1]);
                    mma16816(acc[mt][nt], al, bh[nt * 2], bh[nt * 2 + 1]);
                }
            }
        }
    }

    // writeback
    int r0 = lane >> 2, c2 = (lane & 3) * 2;
#pragma unroll
    for (int mt = 0; mt < 4; mt++) {
#pragma unroll
        for (int nt = 0; nt < 4; nt++) {
            int row = bm + wm + mt * 16 + r0;
            int col = bn + wn + nt * 8 + c2;
            float* cc = acc[mt][nt];
            if (mode == 1) {
                float b0 = bias[col], b1 = bias[col + 1];
                *(float2*)(C + (size_t)row * EMB + col) =
                    make_float2(cc[0] + b0, cc[1] + b1);
                *(float2*)(C + (size_t)(row + 8) * EMB + col) =
                    make_float2(cc[2] + b0, cc[3] + b1);
            } else {
                int h = col >> 6, d = col & 63;
                int b_ = row >> 11, s = row & 2047;
                float* dst = C + ((((size_t)b_ * HEADS + h) * SEQ + s) * HD + d);
                *(float2*)dst = make_float2(cc[0], cc[1]);
                dst += (size_t)8 * HD;     // row+8, same (b,h) since rows stay in-batch
                *(float2*)dst = make_float2(cc[2], cc[3]);
            }
        }
    }
}

// ---------------------------------------------------------------------------
// Causal flash attention (fp32 SIMT). Q,K,V in [b,h,s,d]; O in [b,s,h,d].
// ---------------------------------------------------------------------------
#define BQ 64
#define BK 32

__global__ __launch_bounds__(256)
void attn_kernel(const float* __restrict__ Q, const float* __restrict__ K,
                 const float* __restrict__ V, float* __restrict__ O)
{
    __shared__ float Qs[64][64];
    __shared__ float Ks[64][34];
    __shared__ float Vs[32][64];
    __shared__ float Ps[32][64];

    int tid = threadIdx.x;
    int tx = tid & 15, ty = tid >> 4;
    int bh = blockIdx.y;
    int q0 = blockIdx.x * BQ;

    const float* Qb = Q + (size_t)bh * SEQ * HD;
    const float* Kb = K + (size_t)bh * SEQ * HD;
    const float* Vb = V + (size_t)bh * SEQ * HD;

    {
        int q = tid >> 2;
        int dbase = (tid & 3) * 16;
#pragma unroll
        for (int i = 0; i < 4; i++) {
            float4 v4 = *(const float4*)&Qb[(size_t)(q0 + q) * HD + dbase + i * 4];
            Qs[dbase + i * 4 + 0][q] = v4.x;
            Qs[dbase + i * 4 + 1][q] = v4.y;
            Qs[dbase + i * 4 + 2][q] = v4.z;
            Qs[dbase + i * 4 + 3][q] = v4.w;
        }
    }

    float m_row[4], l_row[4], acc[4][4];
#pragma unroll
    for (int i = 0; i < 4; i++) {
        m_row[i] = -INFINITY; l_row[i] = 0.0f;
#pragma unroll
        for (int j = 0; j < 4; j++) acc[i][j] = 0.0f;
    }

    const float scale = 0.125f;
    int nkb = (q0 + BQ) / BK;
    int kr = tid >> 3;
    int dbase = (tid & 7) * 8;

    for (int kb = 0; kb < nkb; kb++) {
        int k0 = kb * BK;
        float4 kv0 = *(const float4*)&Kb[(size_t)(k0 + kr) * HD + dbase];
        float4 kv1 = *(const float4*)&Kb[(size_t)(k0 + kr) * HD + dbase + 4];
        float4 vv0 = *(const float4*)&Vb[(size_t)(k0 + kr) * HD + dbase];
        float4 vv1 = *(const float4*)&Vb[(size_t)(k0 + kr) * HD + dbase + 4];

        __syncthreads();
        Ks[dbase + 0][kr] = kv0.x; Ks[dbase + 1][kr] = kv0.y;
        Ks[dbase + 2][kr] = kv0.z; Ks[dbase + 3][kr] = kv0.w;
        Ks[dbase + 4][kr] = kv1.x; Ks[dbase + 5][kr] = kv1.y;
        Ks[dbase + 6][kr] = kv1.z; Ks[dbase + 7][kr] = kv1.w;
        *(float4*)&Vs[kr][dbase]     = vv0;
        *(float4*)&Vs[kr][dbase + 4] = vv1;
        __syncthreads();

        float s[4][2];
#pragma unroll
        for (int i = 0; i < 4; i++) { s[i][0] = 0.0f; s[i][1] = 0.0f; }
#pragma unroll
        for (int d = 0; d < 64; d++) {
            float4 a = *(const float4*)&Qs[d][ty * 4];
            float2 b = *(const float2*)&Ks[d][tx * 2];
            s[0][0] += a.x * b.x; s[0][1] += a.x * b.y;
            s[1][0] += a.y * b.x; s[1][1] += a.y * b.y;
            s[2][0] += a.z * b.x; s[2][1] += a.z * b.y;
            s[3][0] += a.w * b.x; s[3][1] += a.w * b.y;
        }

        bool need_mask = (k0 + BK - 1) > q0;
#pragma unroll
        for (int i = 0; i < 4; i++) {
            int qi = q0 + ty * 4 + i;
#pragma unroll
            for (int j = 0; j < 2; j++) {
                s[i][j] *= scale;
                if (need_mask && (k0 + tx * 2 + j) > qi) s[i][j] = -INFINITY;
            }
        }

        float mb[4];
#pragma unroll
        for (int i = 0; i < 4; i++) {
            mb[i] = fmaxf(s[i][0], s[i][1]);
            mb[i] = fmaxf(mb[i], __shfl_xor_sync(0xffffffffu, mb[i], 1));
            mb[i] = fmaxf(mb[i], __shfl_xor_sync(0xffffffffu, mb[i], 2));
            mb[i] = fmaxf(mb[i], __shfl_xor_sync(0xffffffffu, mb[i], 4));
            mb[i] = fmaxf(mb[i], __shfl_xor_sync(0xffffffffu, mb[i], 8));
        }

        float p[4][2];
#pragma unroll
        for (int i = 0; i < 4; i++) {
            float m_new = fmaxf(m_row[i], mb[i]);
            float fac = __expf(m_row[i] - m_new);
            p[i][0] = __expf(s[i][0] - m_new);
            p[i][1] = __expf(s[i][1] - m_new);
            float rs = p[i][0] + p[i][1];
            rs += __shfl_xor_sync(0xffffffffu, rs, 1);
            rs += __shfl_xor_sync(0xffffffffu, rs, 2);
            rs += __shfl_xor_sync(0xffffffffu, rs, 4);
            rs += __shfl_xor_sync(0xffffffffu, rs, 8);
            l_row[i] = l_row[i] * fac + rs;
            m_row[i] = m_new;
            acc[i][0] *= fac; acc[i][1] *= fac; acc[i][2] *= fac; acc[i][3] *= fac;
        }

#pragma unroll
        for (int i = 0; i < 4; i++) {
            Ps[tx * 2 + 0][ty * 4 + i] = p[i][0];
            Ps[tx * 2 + 1][ty * 4 + i] = p[i][1];
        }
        __syncthreads();

#pragma unroll
        for (int j = 0; j < 32; j++) {
            float4 a = *(const float4*)&Ps[j][ty * 4];
            float4 b = *(const float4*)&Vs[j][tx * 4];
            acc[0][0] += a.x * b.x; acc[0][1] += a.x * b.y; acc[0][2] += a.x * b.z; acc[0][3] += a.x * b.w;
            acc[1][0] += a.y * b.x; acc[1][1] += a.y * b.y; acc[1][2] += a.y * b.z; acc[1][3] += a.y * b.w;
            acc[2][0] += a.z * b.x; acc[2][1] += a.z * b.y; acc[2][2] += a.z * b.z; acc[2][3] += a.z * b.w;
            acc[3][0] += a.w * b.x; acc[3][1] += a.w * b.y; acc[3][2] += a.w * b.z; acc[3][3] += a.w * b.w;
        }
    }

    int b = bh >> 4, h = bh & 15;
#pragma unroll
    for (int i = 0; i < 4; i++) {
        float inv = 1.0f / l_row[i];
        int sidx = q0 + ty * 4 + i;
        float4 o = make_float4(acc[i][0] * inv, acc[i][1] * inv,
                               acc[i][2] * inv, acc[i][3] * inv);
        float* dst = O + (((size_t)b * SEQ + sidx) * HEADS + h) * HD + tx * 4;
        *(float4*)dst = o;
    }
}

// ---------------------------------------------------------------------------
extern "C" void kernel_launch(void* const* d_in, const int* in_sizes, int n_in,
                              void* d_out, int out_size)
{
    const float* x  = (const float*)d_in[0];
    const float* Wq = (const float*)d_in[1];
    const float* Wk = (const float*)d_in[2];
    const float* Wv = (const float*)d_in[3];
    const float* Wo = (const float*)d_in[4];
    const float* bo = (const float*)d_in[5];
    float* out = (float*)d_out;

    float *q, *k, *v, *a;
    __nv_bfloat16 *xhi, *xlo, *whi, *wlo, *ahi, *alo;
    cudaGetSymbolAddress((void**)&q, g_q);
    cudaGetSymbolAddress((void**)&k, g_k);
    cudaGetSymbolAddress((void**)&v, g_v);
    cudaGetSymbolAddress((void**)&a, g_a);
    cudaGetSymbolAddress((void**)&xhi, g_xhi);
    cudaGetSymbolAddress((void**)&xlo, g_xlo);
    cudaGetSymbolAddress((void**)&whi, g_whi);
    cudaGetSymbolAddress((void**)&wlo, g_wlo);
    cudaGetSymbolAddress((void**)&ahi, g_ahi);
    cudaGetSymbolAddress((void**)&alo, g_alo);

    cudaFuncSetAttribute(wm_gemm, cudaFuncAttributeMaxDynamicSharedMemorySize, GEMM_SMEM);

    // 1. Split x and all four W into bf16 hi/lo
    conv_split<<<MROWS * EMB / 4 / 256, 256>>>(x, xhi, xlo);
    conv_w4<<<dim3(EMB * EMB / 4 / 256, 4), 256>>>(Wq, Wk, Wv, Wo, whi, wlo);

    // 2. Fused QKV projections on tensor cores (mma.sync)
    dim3 qkv_grid(MROWS / 128, EMB / 128, 3);
    wm_gemm<<<qkv_grid, 256, GEMM_SMEM>>>(xhi, xlo, whi, wlo, q, k, v, nullptr, 0);

    // 3. Causal attention (SIMT fp32)
    dim3 attn_grid(SEQ / BQ, BATCH * HEADS);
    attn_kernel<<<attn_grid, 256>>>(q, k, v, a);

    // 4. Split attention output, then output projection (+bias)
    conv_split<<<MROWS * EMB / 4 / 256, 256>>>(a, ahi, alo);
    dim3 out_grid(MROWS / 128, EMB / 128, 1);
    wm_gemm<<<out_grid, 256, GEMM_SMEM>>>(ahi, alo,
                                          whi + (size_t)3 * EMB * EMB,
                                          wlo + (size_t)3 * EMB * EMB,
                                          out, nullptr, nullptr, bo, 1);
}

// round 5
// speedup vs baseline: 3.4687x; 2.2443x over previous
#include <cuda_runtime.h>
#include <cuda_bf16.h>
#include <math.h>
#include <stdint.h>

// Problem constants
#define BATCH 4
#define SEQ   2048
#define EMB   1024
#define HEADS 16
#define HD    64
#define MROWS (BATCH * SEQ)   // 8192

// bf16 split scratch
__device__ __nv_bfloat16 g_xhi[MROWS * EMB];
__device__ __nv_bfloat16 g_xlo[MROWS * EMB];
__device__ __nv_bfloat16 g_whi[4 * EMB * EMB];
__device__ __nv_bfloat16 g_wlo[4 * EMB * EMB];
__device__ __nv_bfloat16 g_qhi[MROWS * EMB];
__device__ __nv_bfloat16 g_qlo[MROWS * EMB];
__device__ __nv_bfloat16 g_khi[MROWS * EMB];
__device__ __nv_bfloat16 g_klo[MROWS * EMB];
__device__ __nv_bfloat16 g_vhi[MROWS * EMB];
__device__ __nv_bfloat16 g_vlo[MROWS * EMB];
__device__ __nv_bfloat16 g_ahi[MROWS * EMB];
__device__ __nv_bfloat16 g_alo[MROWS * EMB];

// ---------------------------------------------------------------------------
// warp-mma helpers (generic PTX: ldmatrix sm_75+, mma bf16 sm_80+)
// ---------------------------------------------------------------------------
__device__ __forceinline__ uint32_t smem_u32(const void* p) {
    uint32_t a;
    asm("{ .reg .u64 t; cvta.to.shared.u64 t, %1; cvt.u32.u64 %0, t; }" : "=r"(a) : "l"(p));
    return a;
}
__device__ __forceinline__ void ldm_x4(uint32_t* r, uint32_t addr) {
    asm volatile("ldmatrix.sync.aligned.m8n8.x4.shared.b16 {%0,%1,%2,%3}, [%4];"
                 : "=r"(r[0]), "=r"(r[1]), "=r"(r[2]), "=r"(r[3]) : "r"(addr));
}
__device__ __forceinline__ void ldm_x4_t(uint32_t* r, uint32_t addr) {
    asm volatile("ldmatrix.sync.aligned.m8n8.x4.trans.shared.b16 {%0,%1,%2,%3}, [%4];"
                 : "=r"(r[0]), "=r"(r[1]), "=r"(r[2]), "=r"(r[3]) : "r"(addr));
}
__device__ __forceinline__ void mma16816(float* c, const uint32_t* a, uint32_t b0, uint32_t b1) {
    asm volatile(
        "mma.sync.aligned.m16n8k16.row.col.f32.bf16.bf16.f32 "
        "{%0,%1,%2,%3}, {%4,%5,%6,%7}, {%8,%9}, {%0,%1,%2,%3};"
        : "+f"(c[0]), "+f"(c[1]), "+f"(c[2]), "+f"(c[3])
        : "r"(a[0]), "r"(a[1]), "r"(a[2]), "r"(a[3]), "r"(b0), "r"(b1));
}

// fp32 pair -> packed bf16 hi / residual lo  (element0 = low half = first arg)
__device__ __forceinline__ void split2(float a, float b, uint32_t& hi, uint32_t& lo) {
    __nv_bfloat16 ha = __float2bfloat16(a);
    __nv_bfloat16 hb = __float2bfloat16(b);
    __nv_bfloat16 la = __float2bfloat16(a - __bfloat162float(ha));
    __nv_bfloat16 lb = __float2bfloat16(b - __bfloat162float(hb));
    __nv_bfloat162 h2 = __nv_bfloat162(ha, hb);
    __nv_bfloat162 l2 = __nv_bfloat162(la, lb);
    hi = *(uint32_t*)&h2;
    lo = *(uint32_t*)&l2;
}

__global__ void conv_split(const float* __restrict__ in,
                           __nv_bfloat16* __restrict__ hi, __nv_bfloat16* __restrict__ lo) {
    int i = (blockIdx.x * blockDim.x + threadIdx.x) * 4;
    float4 v = *(const float4*)(in + i);
    uint32_t h0, l0, h1, l1;
    split2(v.x, v.y, h0, l0);
    split2(v.z, v.w, h1, l1);
    *(uint2*)((char*)hi + (size_t)i * 2) = make_uint2(h0, h1);
    *(uint2*)((char*)lo + (size_t)i * 2) = make_uint2(l0, l1);
}

__global__ void conv_w4(const float* __restrict__ Wq, const float* __restrict__ Wk,
                        const float* __restrict__ Wv, const float* __restrict__ Wo,
                        __nv_bfloat16* __restrict__ hi, __nv_bfloat16* __restrict__ lo) {
    int z = blockIdx.y;
    const float* W = (z == 0) ? Wq : (z == 1) ? Wk : (z == 2) ? Wv : Wo;
    size_t off = (size_t)z * EMB * EMB;
    int i = (blockIdx.x * blockDim.x + threadIdx.x) * 4;
    float4 v = *(const float4*)(W + i);
    uint32_t h0, l0, h1, l1;
    split2(v.x, v.y, h0, l0);
    split2(v.z, v.w, h1, l1);
    *(uint2*)((char*)(hi + off) + (size_t)i * 2) = make_uint2(h0, h1);
    *(uint2*)((char*)(lo + off) + (size_t)i * 2) = make_uint2(l0, l1);
}

// ---------------------------------------------------------------------------
// Tensor-core GEMM via mma.sync: C[m,n] = sum_k A[m,k]*W[n,k], 3x bf16 split.
// CTA 128x128, 8 warps (2x4), warp tile 64x32, K chunk 64, SMEM pad-72.
// mode 0: z selects weight; writes bf16 hi/lo split scattered to [b,h,s,d].
// mode 1: fp32 row-major + bias.
// ---------------------------------------------------------------------------
#define SA 72
#define GEMM_SMEM (4 * 128 * SA * 2)         // 73728 B

__global__ __launch_bounds__(256, 1)
void wm_gemm(const __nv_bfloat16* __restrict__ Ahi, const __nv_bfloat16* __restrict__ Alo,
             const __nv_bfloat16* __restrict__ Whi, const __nv_bfloat16* __restrict__ Wlo,
             float* __restrict__ C0, float* __restrict__ C1, float* __restrict__ C2,
             __nv_bfloat16* __restrict__ L0, __nv_bfloat16* __restrict__ L1,
             __nv_bfloat16* __restrict__ L2,
             const float* __restrict__ bias, int mode)
{
    extern __shared__ char smem[];
    char* sAh = smem;
    char* sAl = smem + 128 * SA * 2;
    char* sBh = smem + 2 * 128 * SA * 2;
    char* sBl = smem + 3 * 128 * SA * 2;

    int tid = threadIdx.x, lane = tid & 31, wid = tid >> 5;
    int wm = (wid >> 2) * 64;
    int wn = (wid & 3) * 32;
    int bm = blockIdx.x * 128, bn = blockIdx.y * 128;
    int z = blockIdx.z;
    const char* gAh = (const char*)(Ahi + (size_t)bm * EMB);
    const char* gAl = (const char*)(Alo + (size_t)bm * EMB);
    const char* gBh = (const char*)(Whi + (size_t)z * EMB * EMB + (size_t)bn * EMB);
    const char* gBl = (const char*)(Wlo + (size_t)z * EMB * EMB + (size_t)bn * EMB);
    float* Cf = (z == 0) ? C0 : (z == 1) ? C1 : C2;
    __nv_bfloat16* Clo = (z == 0) ? L0 : (z == 1) ? L1 : L2;

    float acc[4][4][4];
#pragma unroll
    for (int mt = 0; mt < 4; mt++)
#pragma unroll
        for (int nt = 0; nt < 4; nt++)
#pragma unroll
            for (int e = 0; e < 4; e++) acc[mt][nt][e] = 0.0f;

    uint32_t uAh = smem_u32(sAh), uAl = smem_u32(sAl);
    uint32_t uBh = smem_u32(sBh), uBl = smem_u32(sBl);

    uint32_t aoff = (uint32_t)((lane & 15) * SA + (lane >> 4) * 8) * 2;
    uint32_t boff = (uint32_t)(((lane >> 4) * 8 + (lane & 7)) * SA + ((lane >> 3) & 1) * 8) * 2;

    int crow = tid >> 3, cseg = tid & 7;

    for (int c = 0; c < 16; c++) {
        size_t goff = (size_t)c * 128;
        uint4 va[4], vb[4], vc[4], vd[4];
#pragma unroll
        for (int i = 0; i < 4; i++) {
            size_t so = (size_t)(crow + i * 32) * 2048 + goff + cseg * 16;
            va[i] = *(const uint4*)(gAh + so);
            vb[i] = *(const uint4*)(gAl + so);
            vc[i] = *(const uint4*)(gBh + so);
            vd[i] = *(const uint4*)(gBl + so);
        }
        __syncthreads();
#pragma unroll
        for (int i = 0; i < 4; i++) {
            uint32_t doff = (uint32_t)(crow + i * 32) * (SA * 2) + cseg * 16;
            *(uint4*)(sAh + doff) = va[i];
            *(uint4*)(sAl + doff) = vb[i];
            *(uint4*)(sBh + doff) = vc[i];
            *(uint4*)(sBl + doff) = vd[i];
        }
        __syncthreads();

#pragma unroll
        for (int kk = 0; kk < 4; kk++) {
            uint32_t kb = (uint32_t)(kk * 16) * 2;
            uint32_t bh[8], bl[8];
            ldm_x4(bh + 0, uBh + boff + (uint32_t)(wn)      * (SA * 2) + kb);
            ldm_x4(bh + 4, uBh + boff + (uint32_t)(wn + 16) * (SA * 2) + kb);
            ldm_x4(bl + 0, uBl + boff + (uint32_t)(wn)      * (SA * 2) + kb);
            ldm_x4(bl + 4, uBl + boff + (uint32_t)(wn + 16) * (SA * 2) + kb);
#pragma unroll
            for (int mt = 0; mt < 4; mt++) {
                uint32_t ah[4], al[4];
                uint32_t arow = aoff + (uint32_t)(wm + mt * 16) * (SA * 2) + kb;
                ldm_x4(ah, uAh + arow);
                ldm_x4(al, uAl + arow);
#pragma unroll
                for (int nt = 0; nt < 4; nt++) {
                    mma16816(acc[mt][nt], ah, bh[nt * 2], bh[nt * 2 + 1]);
                    mma16816(acc[mt][nt], ah, bl[nt * 2], bl[nt * 2 + 1]);
                    mma16816(acc[mt][nt], al, bh[nt * 2], bh[nt * 2 + 1]);
                }
            }
        }
    }

    int r0 = lane >> 2, c2 = (lane & 3) * 2;
#pragma unroll
    for (int mt = 0; mt < 4; mt++) {
#pragma unroll
        for (int nt = 0; nt < 4; nt++) {
            int row = bm + wm + mt * 16 + r0;
            int col = bn + wn + nt * 8 + c2;
            float* cc = acc[mt][nt];
            if (mode == 1) {
                float b0 = bias[col], b1 = bias[col + 1];
                *(float2*)(Cf + (size_t)row * EMB + col) =
                    make_float2(cc[0] + b0, cc[1] + b1);
                *(float2*)(Cf + (size_t)(row + 8) * EMB + col) =
                    make_float2(cc[2] + b0, cc[3] + b1);
            } else {
                __nv_bfloat16* Chi = (__nv_bfloat16*)Cf;
                int h = col >> 6, d = col & 63;
                int b_ = row >> 11, s = row & 2047;
                size_t idx = ((((size_t)b_ * HEADS + h) * SEQ + s) * HD + d);
                uint32_t hi, lo;
                split2(cc[0], cc[1], hi, lo);
                *(uint32_t*)((char*)Chi + idx * 2) = hi;
                *(uint32_t*)((char*)Clo + idx * 2) = lo;
                size_t idx2 = idx + (size_t)8 * HD;
                split2(cc[2], cc[3], hi, lo);
                *(uint32_t*)((char*)Chi + idx2 * 2) = hi;
                *(uint32_t*)((char*)Clo + idx2 * 2) = lo;
            }
        }
    }
}

// ---------------------------------------------------------------------------
// Tensor-core causal flash attention. Q,K,V as bf16 hi/lo in [b,h,s,d].
// Output: bf16 hi/lo in [b,s,h,d]. CTA = 4 warps, BQ=64, BK=64.
// ---------------------------------------------------------------------------
#define SROW 72
#define ATT_TILE (64 * SROW * 2)       // 9216 B
#define ATT_SMEM (6 * ATT_TILE)        // 55296 B

__global__ __launch_bounds__(128, 1)
void attn_tc(const __nv_bfloat16* __restrict__ Qh, const __nv_bfloat16* __restrict__ Ql,
             const __nv_bfloat16* __restrict__ Kh, const __nv_bfloat16* __restrict__ Kl,
             const __nv_bfloat16* __restrict__ Vh, const __nv_bfloat16* __restrict__ Vl,
             __nv_bfloat16* __restrict__ Ohi, __nv_bfloat16* __restrict__ Olo)
{
    extern __shared__ char sm[];
    char* sQh = sm;
    char* sQl = sm + ATT_TILE;
    char* sKh = sm + 2 * ATT_TILE;
    char* sKl = sm + 3 * ATT_TILE;
    char* sVh = sm + 4 * ATT_TILE;
    char* sVl = sm + 5 * ATT_TILE;

    int tid = threadIdx.x, lane = tid & 31, w = tid >> 5;
    int bh = blockIdx.y;
    int qb = (gridDim.x - 1) - blockIdx.x;       // heavy CTAs first
    int q0 = qb * 64;
    size_t base = (size_t)bh * SEQ * HD;

    // ---- load Q tile (64 x 64 bf16, 128 B/row) ----
    {
        const char* gqh = (const char*)(Qh + base + (size_t)q0 * HD);
        const char* gql = (const char*)(Ql + base + (size_t)q0 * HD);
#pragma unroll
        for (int i = 0; i < 4; i++) {
            int idx = i * 128 + tid;
            int r = idx >> 3, s = idx & 7;
            *(uint4*)(sQh + r * (SROW * 2) + s * 16) = *(const uint4*)(gqh + r * 128 + s * 16);
            *(uint4*)(sQl + r * (SROW * 2) + s * 16) = *(const uint4*)(gql + r * 128 + s * 16);
        }
    }
    __syncthreads();

    uint32_t uQh = smem_u32(sQh), uQl = smem_u32(sQl);
    uint32_t uKh = smem_u32(sKh), uKl = smem_u32(sKl);
    uint32_t uVh = smem_u32(sVh), uVl = smem_u32(sVl);

    // preload Q fragments (warp rows w*16..w*16+15, 4 k-steps)
    uint32_t qh[4][4], ql[4][4];
    {
        uint32_t aoff = (uint32_t)((w * 16 + (lane & 15)) * SROW + (lane >> 4) * 8) * 2;
#pragma unroll
        for (int t = 0; t < 4; t++) {
            ldm_x4(qh[t], uQh + aoff + t * 32);
            ldm_x4(ql[t], uQl + aoff + t * 32);
        }
    }

    float of[8][4];
#pragma unroll
    for (int dt = 0; dt < 8; dt++)
#pragma unroll
        for (int e = 0; e < 4; e++) of[dt][e] = 0.0f;
    float m0 = -INFINITY, m1 = -INFINITY, l0 = 0.0f, l1 = 0.0f;

    const float SC = 0.125f * 1.44269504f;     // scale * log2(e)
    int nkb = qb + 1;

    for (int kb = 0; kb < nkb; kb++) {
        int k0 = kb * 64;
        __syncthreads();
        {
            const char* gkh = (const char*)(Kh + base + (size_t)k0 * HD);
            const char* gkl = (const char*)(Kl + base + (size_t)k0 * HD);
            const char* gvh = (const char*)(Vh + base + (size_t)k0 * HD);
            const char* gvl = (const char*)(Vl + base + (size_t)k0 * HD);
#pragma unroll
            for (int i = 0; i < 4; i++) {
                int idx = i * 128 + tid;
                int r = idx >> 3, s = idx & 7;
                uint32_t doff = r * (SROW * 2) + s * 16;
                size_t go = (size_t)r * 128 + s * 16;
                *(uint4*)(sKh + doff) = *(const uint4*)(gkh + go);
                *(uint4*)(sKl + doff) = *(const uint4*)(gkl + go);
                *(uint4*)(sVh + doff) = *(const uint4*)(gvh + go);
                *(uint4*)(sVl + doff) = *(const uint4*)(gvl + go);
            }
        }
        __syncthreads();

        // ---- S = Q K^T (3x split) ----
        float sf[8][4];
#pragma unroll
        for (int nt = 0; nt < 8; nt++)
#pragma unroll
            for (int e = 0; e < 4; e++) sf[nt][e] = 0.0f;

#pragma unroll
        for (int t = 0; t < 4; t++) {
#pragma unroll
            for (int g = 0; g < 4; g++) {
                uint32_t bo = (uint32_t)((g * 16 + (lane >> 4) * 8 + (lane & 7)) * SROW
                                         + t * 16 + ((lane >> 3) & 1) * 8) * 2;
                uint32_t bhh[4], bll[4];
                ldm_x4(bhh, uKh + bo);
                ldm_x4(bll, uKl + bo);
                mma16816(sf[2 * g],     qh[t], bhh[0], bhh[1]);
                mma16816(sf[2 * g + 1], qh[t], bhh[2], bhh[3]);
                mma16816(sf[2 * g],     qh[t], bll[0], bll[1]);
                mma16816(sf[2 * g + 1], qh[t], bll[2], bll[3]);
                mma16816(sf[2 * g],     ql[t], bhh[0], bhh[1]);
                mma16816(sf[2 * g + 1], ql[t], bhh[2], bhh[3]);
            }
        }

        // ---- scale (+ diagonal mask), online softmax ----
        if (kb == qb) {
            int qr0 = q0 + w * 16 + (lane >> 2);
            int jb  = k0 + (lane & 3) * 2;
#pragma unroll
            for (int nt = 0; nt < 8; nt++) {
                int j = jb + nt * 8;
                sf[nt][0] = (j     > qr0)     ? -INFINITY : sf[nt][0] * SC;
                sf[nt][1] = (j + 1 > qr0)     ? -INFINITY : sf[nt][1] * SC;
                sf[nt][2] = (j     > qr0 + 8) ? -INFINITY : sf[nt][2] * SC;
                sf[nt][3] = (j + 1 > qr0 + 8) ? -INFINITY : sf[nt][3] * SC;
            }
        } else {
#pragma unroll
            for (int nt = 0; nt < 8; nt++)
#pragma unroll
                for (int e = 0; e < 4; e++) sf[nt][e] *= SC;
        }

        float bm0 = -INFINITY, bm1 = -INFINITY;
#pragma unroll
        for (int nt = 0; nt < 8; nt++) {
            bm0 = fmaxf(bm0, fmaxf(sf[nt][0], sf[nt][1]));
            bm1 = fmaxf(bm1, fmaxf(sf[nt][2], sf[nt][3]));
        }
        bm0 = fmaxf(bm0, __shfl_xor_sync(0xffffffffu, bm0, 1));
        bm0 = fmaxf(bm0, __shfl_xor_sync(0xffffffffu, bm0, 2));
        bm1 = fmaxf(bm1, __shfl_xor_sync(0xffffffffu, bm1, 1));
        bm1 = fmaxf(bm1, __shfl_xor_sync(0xffffffffu, bm1, 2));

        float mn0 = fmaxf(m0, bm0), mn1 = fmaxf(m1, bm1);
        float f0 = exp2f(m0 - mn0), f1 = exp2f(m1 - mn1);
        float rs0 = 0.0f, rs1 = 0.0f;
#pragma unroll
        for (int nt = 0; nt < 8; nt++) {
            sf[nt][0] = exp2f(sf[nt][0] - mn0);
            sf[nt][1] = exp2f(sf[nt][1] - mn0);
            sf[nt][2] = exp2f(sf[nt][2] - mn1);
            sf[nt][3] = exp2f(sf[nt][3] - mn1);
            rs0 += sf[nt][0] + sf[nt][1];
            rs1 += sf[nt][2] + sf[nt][3];
        }
        rs0 += __shfl_xor_sync(0xffffffffu, rs0, 1);
        rs0 += __shfl_xor_sync(0xffffffffu, rs0, 2);
        rs1 += __shfl_xor_sync(0xffffffffu, rs1, 1);
        rs1 += __shfl_xor_sync(0xffffffffu, rs1, 2);
        l0 = l0 * f0 + rs0;  m0 = mn0;
        l1 = l1 * f1 + rs1;  m1 = mn1;
#pragma unroll
        for (int dt = 0; dt < 8; dt++) {
            of[dt][0] *= f0; of[dt][1] *= f0;
            of[dt][2] *= f1; of[dt][3] *= f1;
        }

        // ---- O += P V (3x split; P fragments straight from sf) ----
#pragma unroll
        for (int t = 0; t < 4; t++) {
            uint32_t pah[4], pal[4];
            split2(sf[2 * t][0],     sf[2 * t][1],     pah[0], pal[0]);
            split2(sf[2 * t][2],     sf[2 * t][3],     pah[1], pal[1]);
            split2(sf[2 * t + 1][0], sf[2 * t + 1][1], pah[2], pal[2]);
            split2(sf[2 * t + 1][2], sf[2 * t + 1][3], pah[3], pal[3]);
            uint32_t vo = (uint32_t)((t * 16 + (lane & 15)) * SROW + (lane >> 4) * 8) * 2;
#pragma unroll
            for (int g = 0; g < 4; g++) {
                uint32_t bvh[4], bvl[4];
                ldm_x4_t(bvh, uVh + vo + g * 32);
                ldm_x4_t(bvl, uVl + vo + g * 32);
                mma16816(of[2 * g],     pah, bvh[0], bvh[1]);
                mma16816(of[2 * g + 1], pah, bvh[2], bvh[3]);
                mma16816(of[2 * g],     pah, bvl[0], bvl[1]);
                mma16816(of[2 * g + 1], pah, bvl[2], bvl[3]);
                mma16816(of[2 * g],     pal, bvh[0], bvh[1]);
                mma16816(of[2 * g + 1], pal, bvh[2], bvh[3]);
            }
        }
    }

    // ---- epilogue: normalize, split, write [b,s,h,d] ----
    float inv0 = 1.0f / l0, inv1 = 1.0f / l1;
    int b = bh >> 4, h = bh & 15;
    int r = q0 + w * 16 + (lane >> 2);
#pragma unroll
    for (int dt = 0; dt < 8; dt++) {
        int d = dt * 8 + (lane & 3) * 2;
        size_t i0 = (((size_t)b * SEQ + r) * HEADS + h) * HD + d;
        size_t i1 = i0 + (size_t)8 * HEADS * HD;
        uint32_t hi, lo;
        split2(of[dt][0] * inv0, of[dt][1] * inv0, hi, lo);
        *(uint32_t*)((char*)Ohi + i0 * 2) = hi;
        *(uint32_t*)((char*)Olo + i0 * 2) = lo;
        split2(of[dt][2] * inv1, of[dt][3] * inv1, hi, lo);
        *(uint32_t*)((char*)Ohi + i1 * 2) = hi;
        *(uint32_t*)((char*)Olo + i1 * 2) = lo;
    }
}

// ---------------------------------------------------------------------------
extern "C" void kernel_launch(void* const* d_in, const int* in_sizes, int n_in,
                              void* d_out, int out_size)
{
    const float* x  = (const float*)d_in[0];
    const float* Wq = (const float*)d_in[1];
    const float* Wk = (const float*)d_in[2];
    const float* Wv = (const float*)d_in[3];
    const float* Wo = (const float*)d_in[4];
    const float* bo = (const float*)d_in[5];
    float* out = (float*)d_out;

    __nv_bfloat16 *xhi, *xlo, *whi, *wlo;
    __nv_bfloat16 *qhi, *qlo, *khi, *klo, *vhi, *vlo, *ahi, *alo;
    cudaGetSymbolAddress((void**)&xhi, g_xhi);
    cudaGetSymbolAddress((void**)&xlo, g_xlo);
    cudaGetSymbolAddress((void**)&whi, g_whi);
    cudaGetSymbolAddress((void**)&wlo, g_wlo);
    cudaGetSymbolAddress((void**)&qhi, g_qhi);
    cudaGetSymbolAddress((void**)&qlo, g_qlo);
    cudaGetSymbolAddress((void**)&khi, g_khi);
    cudaGetSymbolAddress((void**)&klo, g_klo);
    cudaGetSymbolAddress((void**)&vhi, g_vhi);
    cudaGetSymbolAddress((void**)&vlo, g_vlo);
    cudaGetSymbolAddress((void**)&ahi, g_ahi);
    cudaGetSymbolAddress((void**)&alo, g_alo);

    cudaFuncSetAttribute(wm_gemm, cudaFuncAttributeMaxDynamicSharedMemorySize, GEMM_SMEM);
    cudaFuncSetAttribute(attn_tc, cudaFuncAttributeMaxDynamicSharedMemorySize, ATT_SMEM);

    // 1. split inputs
    conv_split<<<MROWS * EMB / 4 / 256, 256>>>(x, xhi, xlo);
    conv_w4<<<dim3(EMB * EMB / 4 / 256, 4), 256>>>(Wq, Wk, Wv, Wo, whi, wlo);

    // 2. QKV projections -> bf16 hi/lo in [b,h,s,d]
    dim3 qkv_grid(MROWS / 128, EMB / 128, 3);
    wm_gemm<<<qkv_grid, 256, GEMM_SMEM>>>(xhi, xlo, whi, wlo,
                                          (float*)qhi, (float*)khi, (float*)vhi,
                                          qlo, klo, vlo, nullptr, 0);

    // 3. tensor-core causal attention -> bf16 hi/lo in [b,s,h,d]
    dim3 attn_grid(SEQ / 64, BATCH * HEADS);
    attn_tc<<<attn_grid, 128, ATT_SMEM>>>(qhi, qlo, khi, klo, vhi, vlo, ahi, alo);

    // 4. output projection (+bias) -> fp32
    dim3 out_grid(MROWS / 128, EMB / 128, 1);
    wm_gemm<<<out_grid, 256, GEMM_SMEM>>>(ahi, alo,
                                          whi + (size_t)3 * EMB * EMB,
                                          wlo + (size_t)3 * EMB * EMB,
                                          out, nullptr, nullptr,
                                          nullptr, nullptr, nullptr, bo, 1);
}